// round 6
// baseline (speedup 1.0000x reference)
#include <cuda_runtime.h>
#include <math.h>
#include <stdint.h>

// ---------------- shapes ----------------
#define BB     4
#define PP     2048
#define TOK    8192          // BB*PP
#define DM     1024          // d_model
#define NH     16
#define NKV    8
#define HDIM   64
#define FF     4096
#define NE     16
#define FEXP   256
#define BHT    64            // BB*NH

// ---------------- scratch (device globals; no allocation allowed) -------------
__device__ float g_h [ (size_t)TOK * DM ];
__device__ float g_q [ (size_t)TOK * NH * HDIM ];
__device__ float g_k [ (size_t)TOK * NKV * HDIM ];
__device__ float g_v [ (size_t)TOK * NKV * HDIM ];
__device__ float g_S [ (size_t)BHT * PP * PP ];     // 1.07 GB
__device__ float g_o [ (size_t)TOK * NH * HDIM ];
__device__ float g_b1[ (size_t)TOK * FF ];
__device__ float g_b2[ (size_t)TOK * FF ];
__device__ float g_w [ 28311552 ];                  // tf32-rounded weights (113 MB)

// offsets into g_w
#define OFF_WQ 0
#define OFF_WK 1048576
#define OFF_WV 1572864
#define OFF_WO 2097152
#define OFF_WG 3145728
#define OFF_WU 7340032
#define OFF_WD 11534336
#define OFF_EG 15728640
#define OFF_EU 19922944
#define OFF_ED 24117248

// ---------------- tf32 helpers ----------------
__device__ __forceinline__ float tf32r(float x) {
    uint32_t r;
    asm("cvt.rna.tf32.f32 %0, %1;" : "=r"(r) : "f"(x));
    return __uint_as_float(r);
}

__device__ __forceinline__ void mma_tf32(float4& d, const uint32_t a[4], const uint32_t b[2]) {
    asm volatile(
        "mma.sync.aligned.m16n8k8.row.col.f32.tf32.tf32.f32 "
        "{%0,%1,%2,%3}, {%4,%5,%6,%7}, {%8,%9}, {%0,%1,%2,%3};\n"
        : "+f"(d.x), "+f"(d.y), "+f"(d.z), "+f"(d.w)
        : "r"(a[0]), "r"(a[1]), "r"(a[2]), "r"(a[3]), "r"(b[0]), "r"(b[1]));
}

__device__ __forceinline__ void cp16(uint32_t dst, const void* src) {
    asm volatile("cp.async.ca.shared.global [%0], [%1], 16;\n" :: "r"(dst), "l"(src));
}
__device__ __forceinline__ void cp16z(uint32_t dst, const void* src, int srcsize) {
    asm volatile("cp.async.ca.shared.global [%0], [%1], 16, %2;\n"
                 :: "r"(dst), "l"(src), "r"(srcsize));
}
__device__ __forceinline__ void cp_commit() { asm volatile("cp.async.commit_group;\n"); }
__device__ __forceinline__ void cp_wait0()  { asm volatile("cp.async.wait_group 0;\n"); }
__device__ __forceinline__ void cp_wait1()  { asm volatile("cp.async.wait_group 1;\n"); }

// ---------------- tf32 GEMM core ----------------
// BM=128, BN=128, BK=32, 256 threads (8 warps in 4x2), warp tile 32x64.
// All operands must already be tf32-rounded (low 13 bits zero) — frag loads are raw LDS.
#define AS_ELEMS (2*128*36)
#define BS_NN_ELEMS (2*32*132)
#define BS_TB_ELEMS (2*128*36)
#define SMEM_NN_BYTES ((AS_ELEMS + BS_NN_ELEMS)*4)
#define SMEM_TB_BYTES ((AS_ELEMS + BS_TB_ELEMS)*4)

template<bool TRANSB>
__device__ __forceinline__ void tf32_core(
    const float* __restrict__ A, int lda,
    const float* __restrict__ B, int ldb,
    float* __restrict__ C, int ldc,
    const float* __restrict__ bias,
    const float* __restrict__ R, int ldr,
    int accumulate, int round_out, int N, int K, float alpha, int m0, int n0)
{
    extern __shared__ float smf[];
    float* As  = smf;
    float* Bsm = smf + AS_ELEMS;

    const int tid  = threadIdx.x;
    const int lane = tid & 31;
    const int warp = tid >> 5;
    const int wm   = (warp >> 1) * 32;
    const int wn   = (warp & 1) * 64;
    const int g    = lane >> 2;
    const int t    = lane & 3;

    uint32_t As_u = (uint32_t)__cvta_generic_to_shared(As);
    uint32_t Bs_u = (uint32_t)__cvta_generic_to_shared(Bsm);

    float4 acc[2][8];
#pragma unroll
    for (int i = 0; i < 2; i++)
#pragma unroll
        for (int j = 0; j < 8; j++) acc[i][j] = make_float4(0.f, 0.f, 0.f, 0.f);

    const int niter = K >> 5;

    auto issue = [&](int it) {
        int buf = it & 1;
        int k0  = it << 5;
#pragma unroll
        for (int l = 0; l < 4; l++) {
            int chunk = tid + l * 256;
            int row = chunk >> 3;
            int kk  = (chunk & 7) << 2;
            cp16(As_u + (((buf << 7) + row) * 36 + kk) * 4,
                 A + (long long)(m0 + row) * lda + k0 + kk);
        }
        if (TRANSB) {
#pragma unroll
            for (int l = 0; l < 4; l++) {
                int chunk = tid + l * 256;
                int row = chunk >> 3;
                int kk  = (chunk & 7) << 2;
                cp16(Bs_u + (((buf << 7) + row) * 36 + kk) * 4,
                     B + (long long)(n0 + row) * ldb + k0 + kk);
            }
        } else {
#pragma unroll
            for (int l = 0; l < 4; l++) {
                int chunk = tid + l * 256;
                int kk = chunk >> 5;
                int nn = (chunk & 31) << 2;
                int sz = (n0 + nn < N) ? 16 : 0;
                cp16z(Bs_u + ((buf * 32 + kk) * 132 + nn) * 4,
                      B + (long long)(k0 + kk) * ldb + n0 + nn, sz);
            }
        }
        cp_commit();
    };

    issue(0);
    for (int it = 0; it < niter; ++it) {
        if (it + 1 < niter) { issue(it + 1); cp_wait1(); }
        else                { cp_wait0(); }
        __syncthreads();

        const uint32_t* Ab = (const uint32_t*)(As + (it & 1) * (128 * 36));
        const uint32_t* Bb = (const uint32_t*)(TRANSB ? (Bsm + (it & 1) * (128 * 36))
                                                      : (Bsm + (it & 1) * (32 * 132)));
#pragma unroll
        for (int ks = 0; ks < 4; ks++) {
            int k = ks * 8;
            uint32_t af[2][4];
#pragma unroll
            for (int tm = 0; tm < 2; tm++) {
                int r = wm + tm * 16;
                af[tm][0] = Ab[(r + g)     * 36 + k + t];
                af[tm][1] = Ab[(r + 8 + g) * 36 + k + t];
                af[tm][2] = Ab[(r + g)     * 36 + k + 4 + t];
                af[tm][3] = Ab[(r + 8 + g) * 36 + k + 4 + t];
            }
            uint32_t bf[8][2];
#pragma unroll
            for (int tn = 0; tn < 8; tn++) {
                int c = wn + tn * 8;
                if (TRANSB) {
                    bf[tn][0] = Bb[(c + g) * 36 + k + t];
                    bf[tn][1] = Bb[(c + g) * 36 + k + 4 + t];
                } else {
                    bf[tn][0] = Bb[(k + t)     * 132 + c + g];
                    bf[tn][1] = Bb[(k + 4 + t) * 132 + c + g];
                }
            }
#pragma unroll
            for (int tm = 0; tm < 2; tm++)
#pragma unroll
                for (int tn = 0; tn < 8; tn++)
                    mma_tf32(acc[tm][tn], af[tm], bf[tn]);
        }
        __syncthreads();
    }

    // epilogue
#pragma unroll
    for (int tm = 0; tm < 2; tm++) {
        int r0 = m0 + wm + tm * 16 + g;
#pragma unroll
        for (int tn = 0; tn < 8; tn++) {
            int c0 = n0 + wn + tn * 8 + t * 2;
            float4 d = acc[tm][tn];
            float vals[4] = { d.x, d.y, d.z, d.w };
            int   rows[4] = { r0, r0, r0 + 8, r0 + 8 };
            int   cols[4] = { c0, c0 + 1, c0, c0 + 1 };
#pragma unroll
            for (int e = 0; e < 4; e++) {
                int col = cols[e];
                if (col < N) {
                    float vv = vals[e] * alpha;
                    if (bias) vv += bias[col];
                    if (R)    vv += R[(long long)rows[e] * ldr + col];
                    if (round_out) vv = tf32r(vv);
                    long long ci = (long long)rows[e] * ldc + col;
                    if (accumulate) C[ci] += vv; else C[ci] = vv;
                }
            }
        }
    }
}

struct GemmArgs {
    const float* A; const float* B; float* C; const float* bias; const float* R;
    long long sAz, sBz, sCz, sRz;
    int lda, ldb, ldc, ldr;
    int N, K;
    float alpha;
    int accumulate;
    int round_out;
};

__global__ void __launch_bounds__(256, 2) tf32_gemm_nn_k(GemmArgs a) {
    int z = blockIdx.z;
    const float* A = a.A + (long long)z * a.sAz;
    const float* B = a.B + (long long)z * a.sBz;
    float*       C = a.C + (long long)z * a.sCz;
    const float* R = a.R ? a.R + (long long)z * a.sRz : (const float*)0;
    tf32_core<false>(A, a.lda, B, a.ldb, C, a.ldc, a.bias, R, a.ldr,
                     a.accumulate, a.round_out, a.N, a.K, a.alpha,
                     blockIdx.y * 128, blockIdx.x * 128);
}

// S[bh] = (1/8) * Q[b,:,h,:] @ K[b,:,h/2,:]^T  with causal block skip
__global__ void __launch_bounds__(256, 2) attn_s_k(const float* __restrict__ q,
                                                   const float* __restrict__ k,
                                                   float* __restrict__ S)
{
    int z = blockIdx.z;
    int b = z / NH, h = z % NH;
    int m0 = blockIdx.y * 128, n0 = blockIdx.x * 128;
    if (n0 > m0 + 127) return;
    const float* A = q + (long long)b * PP * (NH * HDIM) + h * HDIM;
    const float* B = k + (long long)b * PP * (NKV * HDIM) + (h >> 1) * HDIM;
    float*       C = S + (long long)z * PP * PP;
    tf32_core<true>(A, NH * HDIM, B, NKV * HDIM, C, PP,
                    (const float*)0, (const float*)0, 0,
                    0, 0, PP, HDIM, 0.125f, m0, n0);
}

// O[b,:,h,:] = P[bh] @ V[b,:,h/2,:]  (K clipped to causal bound; masked probs are 0)
__global__ void __launch_bounds__(256, 2) attn_pv_k(const float* __restrict__ S,
                                                    const float* __restrict__ v,
                                                    float* __restrict__ o)
{
    int z = blockIdx.z;
    int b = z / NH, h = z % NH;
    int m0 = blockIdx.y * 128;
    const float* A = S + (long long)z * PP * PP;
    const float* B = v + (long long)b * PP * (NKV * HDIM) + (h >> 1) * HDIM;
    float*       C = o + (long long)b * PP * (NH * HDIM) + h * HDIM;
    int Keff = m0 + 128;
    tf32_core<false>(A, PP, B, NKV * HDIM, C, NH * HDIM,
                     (const float*)0, (const float*)0, 0,
                     0, /*round o for wo GEMM*/1, HDIM, Keff, 1.0f, m0, 0);
}

// ---------------- elementwise kernels ----------------
// weight tf32 pre-round (vectorized)
__global__ void cvtw_k(const float4* __restrict__ in, float4* __restrict__ out, int n4)
{
    int i = blockIdx.x * blockDim.x + threadIdx.x;
    if (i >= n4) return;
    float4 v = in[i];
    v.x = tf32r(v.x); v.y = tf32r(v.y); v.z = tf32r(v.z); v.w = tf32r(v.w);
    out[i] = v;
}

__global__ void rmsnorm_k(const float* __restrict__ x, const float* __restrict__ w,
                          float* __restrict__ y)
{
    long long base = (long long)blockIdx.x * DM;
    int tid = threadIdx.x;
    float vv[4];
    float ss = 0.0f;
#pragma unroll
    for (int l = 0; l < 4; l++) {
        vv[l] = x[base + tid + l * 256];
        ss += vv[l] * vv[l];
    }
    __shared__ float sm[256];
    sm[tid] = ss; __syncthreads();
    for (int s = 128; s > 0; s >>= 1) {
        if (tid < s) sm[tid] += sm[tid + s];
        __syncthreads();
    }
    float scale = rsqrtf(sm[0] / (float)DM + 1e-6f);
#pragma unroll
    for (int l = 0; l < 4; l++) {
        int c = tid + l * 256;
        y[base + c] = tf32r(vv[l] * scale * w[c]);
    }
}

__global__ void rope_k(float* __restrict__ buf, int nheads)
{
    int idx = blockIdx.x * blockDim.x + threadIdx.x;
    int total = TOK * nheads * (HDIM / 2);
    if (idx >= total) return;
    int i   = idx & 31;
    int rem = idx >> 5;
    int hh  = rem % nheads;
    int t   = rem / nheads;
    int p   = t & (PP - 1);
    float inv = expf(-(float)i * (1.0f / 32.0f) * 9.210340371976184f);
    float ang = (float)p * inv;
    float c = cosf(ang), s = sinf(ang);
    float* base = buf + ((long long)t * nheads + hh) * HDIM;
    float v1 = base[i], v2 = base[i + 32];
    base[i]      = tf32r(v1 * c - v2 * s);
    base[i + 32] = tf32r(v2 * c + v1 * s);
}

__global__ void softmax_causal_k(float* __restrict__ S)
{
    int p  = blockIdx.x;
    int bh = blockIdx.y;
    float* row = S + ((long long)bh * PP + p) * PP;
    int tid = threadIdx.x;
    float vals[8];
    float mx = -3.0e38f;
#pragma unroll
    for (int l = 0; l < 8; l++) {
        int c = tid + l * 256;
        float v = row[c];
        if (c > p) v = -1.0e9f;
        vals[l] = v;
        mx = fmaxf(mx, v);
    }
    __shared__ float sm[256];
    sm[tid] = mx; __syncthreads();
    for (int s = 128; s > 0; s >>= 1) {
        if (tid < s) sm[tid] = fmaxf(sm[tid], sm[tid + s]);
        __syncthreads();
    }
    mx = sm[0]; __syncthreads();
    float sum = 0.0f;
#pragma unroll
    for (int l = 0; l < 8; l++) {
        vals[l] = expf(vals[l] - mx);
        sum += vals[l];
    }
    sm[tid] = sum; __syncthreads();
    for (int s = 128; s > 0; s >>= 1) {
        if (tid < s) sm[tid] += sm[tid + s];
        __syncthreads();
    }
    float inv = 1.0f / sm[0];
#pragma unroll
    for (int l = 0; l < 8; l++)
        row[tid + l * 256] = tf32r(vals[l] * inv);
}

__global__ void silu_mul_k(const float* __restrict__ g, const float* __restrict__ u,
                           float* __restrict__ out, long long n)
{
    long long i = (long long)blockIdx.x * blockDim.x + threadIdx.x;
    if (i >= n) return;
    float x = g[i];
    float s = x / (1.0f + expf(-x));
    out[i] = tf32r(s * u[i]);
}

__global__ void expert_act_k(const float* __restrict__ g, const float* __restrict__ u,
                             const float* __restrict__ mask, float* __restrict__ out)
{
    long long i = (long long)blockIdx.x * blockDim.x + threadIdx.x;
    if (i >= (long long)TOK * (NE * FEXP)) return;
    long long t = i >> 12;
    int col = (int)(i & (NE * FEXP - 1));
    int e = col >> 8;
    float x = g[i];
    float s = x / (1.0f + expf(-x));
    out[i] = tf32r(s * u[i] * mask[t * NE + e]);
}

// ---------------- host side ----------------
static void launch_gemm(const float* A, long long sAz, int lda,
                        const float* B, long long sBz, int ldb,
                        float* C, long long sCz, int ldc,
                        const float* bias, const float* R, long long sRz, int ldr,
                        int M, int N, int K, float alpha, int acc, int rnd, int batch)
{
    GemmArgs a;
    a.A = A; a.B = B; a.C = C; a.bias = bias; a.R = R;
    a.sAz = sAz; a.sBz = sBz; a.sCz = sCz; a.sRz = sRz;
    a.lda = lda; a.ldb = ldb; a.ldc = ldc; a.ldr = ldr;
    a.N = N; a.K = K; a.alpha = alpha; a.accumulate = acc; a.round_out = rnd;
    dim3 grid((N + 127) / 128, M / 128, batch);
    tf32_gemm_nn_k<<<grid, 256, SMEM_NN_BYTES>>>(a);
}

static void launch_cvtw(const float* src, float* dst, int n)
{
    int n4 = n >> 2;
    cvtw_k<<<(n4 + 255) / 256, 256>>>((const float4*)src, (float4*)dst, n4);
}

extern "C" void kernel_launch(void* const* d_in, const int* in_sizes, int n_in,
                              void* d_out, int out_size)
{
    const float* x           = (const float*)d_in[0];
    const float* expert_mask = (const float*)d_in[1];
    const float* ln1_w       = (const float*)d_in[2];
    const float* wq          = (const float*)d_in[3];
    const float* bq          = (const float*)d_in[4];
    const float* wk          = (const float*)d_in[5];
    const float* bk          = (const float*)d_in[6];
    const float* wv          = (const float*)d_in[7];
    const float* bv          = (const float*)d_in[8];
    const float* wo          = (const float*)d_in[9];
    const float* ln2_w       = (const float*)d_in[10];
    const float* w_gate      = (const float*)d_in[11];
    const float* w_up        = (const float*)d_in[12];
    const float* w_down      = (const float*)d_in[13];
    const float* we_gate     = (const float*)d_in[14];
    const float* we_up       = (const float*)d_in[15];
    const float* we_down     = (const float*)d_in[16];
    float* out = (float*)d_out;

    cudaFuncSetAttribute(tf32_gemm_nn_k, cudaFuncAttributeMaxDynamicSharedMemorySize, SMEM_NN_BYTES);
    cudaFuncSetAttribute(attn_s_k,       cudaFuncAttributeMaxDynamicSharedMemorySize, SMEM_TB_BYTES);
    cudaFuncSetAttribute(attn_pv_k,      cudaFuncAttributeMaxDynamicSharedMemorySize, SMEM_NN_BYTES);

    float *h, *q, *k, *v, *S, *o, *b1, *b2, *w;
    cudaGetSymbolAddress((void**)&h,  g_h);
    cudaGetSymbolAddress((void**)&q,  g_q);
    cudaGetSymbolAddress((void**)&k,  g_k);
    cudaGetSymbolAddress((void**)&v,  g_v);
    cudaGetSymbolAddress((void**)&S,  g_S);
    cudaGetSymbolAddress((void**)&o,  g_o);
    cudaGetSymbolAddress((void**)&b1, g_b1);
    cudaGetSymbolAddress((void**)&b2, g_b2);
    cudaGetSymbolAddress((void**)&w,  g_w);

    // 0. pre-round all mma B-operand weights to tf32
    launch_cvtw(wq,      w + OFF_WQ, DM * NH * HDIM);
    launch_cvtw(wk,      w + OFF_WK, DM * NKV * HDIM);
    launch_cvtw(wv,      w + OFF_WV, DM * NKV * HDIM);
    launch_cvtw(wo,      w + OFF_WO, NH * HDIM * DM);
    launch_cvtw(w_gate,  w + OFF_WG, DM * FF);
    launch_cvtw(w_up,    w + OFF_WU, DM * FF);
    launch_cvtw(w_down,  w + OFF_WD, FF * DM);
    launch_cvtw(we_gate, w + OFF_EG, NE * DM * FEXP);
    launch_cvtw(we_up,   w + OFF_EU, NE * DM * FEXP);
    launch_cvtw(we_down, w + OFF_ED, NE * FEXP * DM);

    // 1. h = rmsnorm(x, ln1_w)  (tf32-rounded)
    rmsnorm_k<<<TOK, 256>>>(x, ln1_w, h);

    // 2. q/k/v projections (+bias); v rounded for PV mma, q/k rounded by rope
    launch_gemm(h, 0, DM, w + OFF_WQ, 0, NH * HDIM,  q, 0, NH * HDIM,  bq, 0, 0, 0,
                TOK, NH * HDIM,  DM, 1.0f, 0, 0, 1);
    launch_gemm(h, 0, DM, w + OFF_WK, 0, NKV * HDIM, k, 0, NKV * HDIM, bk, 0, 0, 0,
                TOK, NKV * HDIM, DM, 1.0f, 0, 0, 1);
    launch_gemm(h, 0, DM, w + OFF_WV, 0, NKV * HDIM, v, 0, NKV * HDIM, bv, 0, 0, 0,
                TOK, NKV * HDIM, DM, 1.0f, 0, 1, 1);

    // 3. RoPE on q and k (rounds all elements)
    rope_k<<<(TOK * NH  * 32 + 255) / 256, 256>>>(q, NH);
    rope_k<<<(TOK * NKV * 32 + 255) / 256, 256>>>(k, NKV);

    // 4. S = QK^T / 8  (causal block skip)
    {
        dim3 grid(PP / 128, PP / 128, BHT);
        attn_s_k<<<grid, 256, SMEM_TB_BYTES>>>(q, k, S);
    }

    // 5. causal softmax in-place (rounds probs)
    {
        dim3 grid(PP, BHT);
        softmax_causal_k<<<grid, 256>>>(S);
    }

    // 6. O = P @ V (epilogue rounds o)
    {
        dim3 grid(1, PP / 128, BHT);
        attn_pv_k<<<grid, 256, SMEM_NN_BYTES>>>(S, v, o);
    }

    // 7. out = x + O @ wo
    launch_gemm(o, 0, NH * HDIM, w + OFF_WO, 0, DM, out, 0, DM,
                (const float*)0, x, 0, DM,
                TOK, DM, NH * HDIM, 1.0f, 0, 0, 1);

    // 8. h2 = rmsnorm(out, ln2_w)
    rmsnorm_k<<<TOK, 256>>>(out, ln2_w, h);

    // 9. dense MLP
    launch_gemm(h, 0, DM, w + OFF_WG, 0, FF, b1, 0, FF, (const float*)0,
                (const float*)0, 0, 0, TOK, FF, DM, 1.0f, 0, 0, 1);
    launch_gemm(h, 0, DM, w + OFF_WU, 0, FF, b2, 0, FF, (const float*)0,
                (const float*)0, 0, 0, TOK, FF, DM, 1.0f, 0, 0, 1);
    {
        long long n = (long long)TOK * FF;
        silu_mul_k<<<(unsigned)((n + 255) / 256), 256>>>(b1, b2, b1, n);
    }
    launch_gemm(b1, 0, FF, w + OFF_WD, 0, DM, out, 0, DM, (const float*)0,
                (const float*)0, 0, 0, TOK, DM, FF, 1.0f, 1, 0, 1);

    // 10. experts (batched over e)
    launch_gemm(h, 0, DM, w + OFF_EG, (long long)DM * FEXP, FEXP,
                b1, FEXP, NE * FEXP, (const float*)0, (const float*)0, 0, 0,
                TOK, FEXP, DM, 1.0f, 0, 0, NE);
    launch_gemm(h, 0, DM, w + OFF_EU, (long long)DM * FEXP, FEXP,
                b2, FEXP, NE * FEXP, (const float*)0, (const float*)0, 0, 0,
                TOK, FEXP, DM, 1.0f, 0, 0, NE);

    // 11. routed combine + down
    {
        long long n = (long long)TOK * NE * FEXP;
        expert_act_k<<<(unsigned)((n + 255) / 256), 256>>>(b1, b2, expert_mask, b1);
    }
    launch_gemm(b1, 0, NE * FEXP, w + OFF_ED, 0, DM, out, 0, DM, (const float*)0,
                (const float*)0, 0, 0, TOK, DM, NE * FEXP, 1.0f, 1, 0, 1);
}

// round 8
// speedup vs baseline: 1.1197x; 1.1197x over previous
#include <cuda_runtime.h>
#include <math.h>
#include <stdint.h>

// ---------------- shapes ----------------
#define BB     4
#define PP     2048
#define TOK    8192
#define DM     1024
#define NH     16
#define NKV    8
#define HDIM   64
#define FF     4096
#define NE     16
#define FEXP   256
#define BHT    64

// ---------------- scratch ----------------
__device__ float g_h [ (size_t)TOK * DM ];
__device__ float g_q [ (size_t)TOK * NH * HDIM ];
__device__ float g_k [ (size_t)TOK * NKV * HDIM ];
__device__ float g_v [ (size_t)TOK * NKV * HDIM ];   // stored TRANSPOSED: [b][kv][hd][seq]
__device__ float g_S [ (size_t)BHT * PP * PP ];
__device__ float g_o [ (size_t)TOK * NH * HDIM ];
__device__ float g_b1[ (size_t)TOK * FF ];
__device__ float g_b2[ (size_t)TOK * FF ];
__device__ float g_w [ 28311552 ];                   // tf32-rounded TRANSPOSED weights

#define OFF_WQ 0
#define OFF_WK 1048576
#define OFF_WV 1572864
#define OFF_WO 2097152
#define OFF_WG 3145728
#define OFF_WU 7340032
#define OFF_WD 11534336
#define OFF_EG 15728640
#define OFF_EU 19922944
#define OFF_ED 24117248

// ---------------- helpers ----------------
__device__ __forceinline__ float tf32r(float x) {
    uint32_t r;
    asm("cvt.rna.tf32.f32 %0, %1;" : "=r"(r) : "f"(x));
    return __uint_as_float(r);
}

__device__ __forceinline__ void mma_tf32(float4& d, const uint32_t a[4], const uint32_t b[2]) {
    asm volatile(
        "mma.sync.aligned.m16n8k8.row.col.f32.tf32.tf32.f32 "
        "{%0,%1,%2,%3}, {%4,%5,%6,%7}, {%8,%9}, {%0,%1,%2,%3};\n"
        : "+f"(d.x), "+f"(d.y), "+f"(d.z), "+f"(d.w)
        : "r"(a[0]), "r"(a[1]), "r"(a[2]), "r"(a[3]), "r"(b[0]), "r"(b[1]));
}

__device__ __forceinline__ void ldsm4(uint32_t& r0, uint32_t& r1, uint32_t& r2, uint32_t& r3,
                                      uint32_t addr) {
    asm volatile("ldmatrix.sync.aligned.m8n8.x4.shared.b16 {%0,%1,%2,%3}, [%4];\n"
                 : "=r"(r0), "=r"(r1), "=r"(r2), "=r"(r3) : "r"(addr));
}

__device__ __forceinline__ void cp16(uint32_t dst, const void* src) {
    asm volatile("cp.async.ca.shared.global [%0], [%1], 16;\n" :: "r"(dst), "l"(src));
}
__device__ __forceinline__ void cp16z(uint32_t dst, const void* src, int srcsize) {
    asm volatile("cp.async.ca.shared.global [%0], [%1], 16, %2;\n"
                 :: "r"(dst), "l"(src), "r"(srcsize));
}
__device__ __forceinline__ void cp_commit() { asm volatile("cp.async.commit_group;\n"); }
__device__ __forceinline__ void cp_wait0()  { asm volatile("cp.async.wait_group 0;\n"); }
__device__ __forceinline__ void cp_wait1()  { asm volatile("cp.async.wait_group 1;\n"); }

// ---------------- tf32 TRANSB GEMM core ----------------
// C[M,N] = A[M,K] @ B^T where B is stored [N,K] row-major (ldb = row stride).
// BM=128, BN=128, BK=32, 128 threads (4 warps 2x2), warp tile 64x64.
// All operands pre-rounded to tf32. Frag loads via ldmatrix.x4.
#define SMEM_T_BYTES (2*2*128*36*4)   // As + Bs, double buffered = 73728

__device__ __forceinline__ void tf32t_core(
    const float* __restrict__ A, int lda,
    const float* __restrict__ B, int ldb,
    float* __restrict__ C, int ldc,
    const float* __restrict__ bias,
    const float* __restrict__ R, int ldr,
    int accumulate, int round_out, int vtrans,
    int N, int K, float alpha, int m0, int n0)
{
    extern __shared__ float smf[];
    float* As = smf;                    // [2][128][36]
    float* Bs = smf + 2 * 128 * 36;     // [2][128][36]

    const int tid  = threadIdx.x;       // 0..127
    const int lane = tid & 31;
    const int warp = tid >> 5;          // 0..3
    const int wm   = (warp >> 1) * 64;
    const int wn   = (warp & 1) * 64;
    const int g    = lane >> 2;
    const int t    = lane & 3;

    uint32_t As_u = (uint32_t)__cvta_generic_to_shared(As);
    uint32_t Bs_u = (uint32_t)__cvta_generic_to_shared(Bs);

    // ldmatrix per-lane sub-tile addressing
    const int sub   = lane >> 3;        // submatrix 0..3
    const int rowin = lane & 7;
    const int a_r = (sub & 1) * 8 + rowin;   // row offset within 16-row tm tile
    const int a_c = (sub >> 1) * 4;          // k offset 0 or 4
    const int b_r = (sub >> 1) * 8 + rowin;  // n-row offset within 16-row pair tile
    const int b_c = (sub & 1) * 4;           // k offset 0 or 4

    float4 acc[4][8];
#pragma unroll
    for (int i = 0; i < 4; i++)
#pragma unroll
        for (int j = 0; j < 8; j++) acc[i][j] = make_float4(0.f, 0.f, 0.f, 0.f);

    const int niter = K >> 5;

    auto issue = [&](int it) {
        int buf = it & 1;
        int k0  = it << 5;
#pragma unroll
        for (int l = 0; l < 8; l++) {
            int chunk = tid + l * 128;        // 0..1023
            int row = chunk >> 3;             // 0..127
            int kk  = (chunk & 7) << 2;       // 0,4,...,28
            cp16(As_u + (((buf << 7) + row) * 36 + kk) * 4,
                 A + (long long)(m0 + row) * lda + k0 + kk);
            int ok = (n0 + row < N);
            const float* bsrc = ok ? (B + (long long)(n0 + row) * ldb + k0 + kk) : B;
            cp16z(Bs_u + (((buf << 7) + row) * 36 + kk) * 4, bsrc, ok ? 16 : 0);
        }
        cp_commit();
    };

    issue(0);
    for (int it = 0; it < niter; ++it) {
        if (it + 1 < niter) { issue(it + 1); cp_wait1(); }
        else                { cp_wait0(); }
        __syncthreads();

        uint32_t Ab = As_u + (it & 1) * (128 * 36 * 4);
        uint32_t Bb = Bs_u + (it & 1) * (128 * 36 * 4);
#pragma unroll
        for (int ks = 0; ks < 4; ks++) {
            int k = ks * 8;
            uint32_t af[4][4];
#pragma unroll
            for (int tm = 0; tm < 4; tm++) {
                uint32_t addr = Ab + (((wm + tm * 16 + a_r) * 36) + k + a_c) * 4;
                ldsm4(af[tm][0], af[tm][1], af[tm][2], af[tm][3], addr);
            }
            uint32_t bf[8][2];
#pragma unroll
            for (int p = 0; p < 4; p++) {
                uint32_t addr = Bb + (((wn + p * 16 + b_r) * 36) + k + b_c) * 4;
                ldsm4(bf[2*p][0], bf[2*p][1], bf[2*p+1][0], bf[2*p+1][1], addr);
            }
#pragma unroll
            for (int tm = 0; tm < 4; tm++)
#pragma unroll
                for (int tn = 0; tn < 8; tn++)
                    mma_tf32(acc[tm][tn], af[tm], bf[tn]);
        }
        __syncthreads();
    }

    // epilogue
#pragma unroll
    for (int tm = 0; tm < 4; tm++) {
        int r0 = m0 + wm + tm * 16 + g;
#pragma unroll
        for (int tn = 0; tn < 8; tn++) {
            int c0 = n0 + wn + tn * 8 + t * 2;
            float4 d = acc[tm][tn];
            float vals[4] = { d.x, d.y, d.z, d.w };
            int   rows[4] = { r0, r0, r0 + 8, r0 + 8 };
            int   cols[4] = { c0, c0 + 1, c0, c0 + 1 };
#pragma unroll
            for (int e = 0; e < 4; e++) {
                int col = cols[e];
                if (col < N) {
                    float vv = vals[e] * alpha;
                    if (bias) vv += bias[col];
                    if (R)    vv += R[(long long)rows[e] * ldr + col];
                    if (round_out) vv = tf32r(vv);
                    long long ci;
                    if (vtrans) // v-transpose store: [b][col][seq], b = row>>11
                        ci = (((long long)(rows[e] >> 11) * 512 + col) << 11) + (rows[e] & 2047);
                    else
                        ci = (long long)rows[e] * ldc + col;
                    if (accumulate) C[ci] += vv; else C[ci] = vv;
                }
            }
        }
    }
}

struct GemmArgs {
    const float* A; const float* B; float* C; const float* bias; const float* R;
    long long sAz, sBz, sCz, sRz;
    int lda, ldb, ldc, ldr;
    int N, K;
    float alpha;
    int accumulate;
    int round_out;
    int vtrans;
};

__global__ void __launch_bounds__(128, 2) tf32_gemm_k(GemmArgs a) {
    int z = blockIdx.z;
    const float* A = a.A + (long long)z * a.sAz;
    const float* B = a.B + (long long)z * a.sBz;
    float*       C = a.C + (long long)z * a.sCz;
    const float* R = a.R ? a.R + (long long)z * a.sRz : (const float*)0;
    tf32t_core(A, a.lda, B, a.ldb, C, a.ldc, a.bias, R, a.ldr,
               a.accumulate, a.round_out, a.vtrans, a.N, a.K, a.alpha,
               blockIdx.y * 128, blockIdx.x * 128);
}

// S[bh] = (1/8) * Q @ K^T with causal block skip
__global__ void __launch_bounds__(128, 2) attn_s_k(const float* __restrict__ q,
                                                   const float* __restrict__ k,
                                                   float* __restrict__ S)
{
    int z = blockIdx.z;
    int b = z / NH, h = z % NH;
    int m0 = blockIdx.y * 128, n0 = blockIdx.x * 128;
    if (n0 > m0 + 127) return;
    const float* A = q + (long long)b * PP * (NH * HDIM) + h * HDIM;
    const float* B = k + (long long)b * PP * (NKV * HDIM) + (h >> 1) * HDIM;
    float*       C = S + (long long)z * PP * PP;
    tf32t_core(A, NH * HDIM, B, NKV * HDIM, C, PP,
               (const float*)0, (const float*)0, 0,
               0, 0, 0, PP, HDIM, 0.125f, m0, n0);
}

// O = P @ V using transposed V: v_t[b][kv*64+hd][seq], ldb = PP
__global__ void __launch_bounds__(128, 2) attn_pv_k(const float* __restrict__ S,
                                                    const float* __restrict__ v,
                                                    float* __restrict__ o)
{
    int z = blockIdx.z;
    int b = z / NH, h = z % NH;
    int m0 = blockIdx.y * 128;
    const float* A = S + (long long)z * PP * PP;
    const float* B = v + ((long long)b * 512 + (h >> 1) * HDIM) * PP;
    float*       C = o + (long long)b * PP * (NH * HDIM) + h * HDIM;
    int Keff = m0 + 128;
    tf32t_core(A, PP, B, PP, C, NH * HDIM,
               (const float*)0, (const float*)0, 0,
               0, 1, 0, HDIM, Keff, 1.0f, m0, 0);
}

// ---------------- elementwise kernels ----------------
// transpose + tf32-round: in [K,Nn] -> out [Nn,K], batched over z
__global__ void cvtw_t_k(const float* __restrict__ in, float* __restrict__ out,
                         int K, int Nn)
{
    __shared__ float tile[32][33];
    long long zoff = (long long)blockIdx.z * K * Nn;
    const float* ip = in + zoff;
    float* op = out + zoff;
    int kb = blockIdx.x * 32, nb = blockIdx.y * 32;
    int tx = threadIdx.x, ty = threadIdx.y;
#pragma unroll
    for (int i = ty; i < 32; i += 8)
        tile[i][tx] = ip[(long long)(kb + i) * Nn + nb + tx];
    __syncthreads();
#pragma unroll
    for (int i = ty; i < 32; i += 8)
        op[(long long)(nb + i) * K + kb + tx] = tf32r(tile[tx][i]);
}

__global__ void rmsnorm_k(const float* __restrict__ x, const float* __restrict__ w,
                          float* __restrict__ y)
{
    long long base = (long long)blockIdx.x * DM;
    int tid = threadIdx.x;
    float vv[4];
    float ss = 0.0f;
#pragma unroll
    for (int l = 0; l < 4; l++) {
        vv[l] = x[base + tid + l * 256];
        ss += vv[l] * vv[l];
    }
    __shared__ float sm[256];
    sm[tid] = ss; __syncthreads();
    for (int s = 128; s > 0; s >>= 1) {
        if (tid < s) sm[tid] += sm[tid + s];
        __syncthreads();
    }
    float scale = rsqrtf(sm[0] / (float)DM + 1e-6f);
#pragma unroll
    for (int l = 0; l < 4; l++) {
        int c = tid + l * 256;
        y[base + c] = tf32r(vv[l] * scale * w[c]);
    }
}

__global__ void rope_k(float* __restrict__ buf, int nheads)
{
    int idx = blockIdx.x * blockDim.x + threadIdx.x;
    int total = TOK * nheads * (HDIM / 2);
    if (idx >= total) return;
    int i   = idx & 31;
    int rem = idx >> 5;
    int hh  = rem % nheads;
    int t   = rem / nheads;
    int p   = t & (PP - 1);
    float inv = expf(-(float)i * (1.0f / 32.0f) * 9.210340371976184f);
    float ang = (float)p * inv;
    float c = cosf(ang), s = sinf(ang);
    float* base = buf + ((long long)t * nheads + hh) * HDIM;
    float v1 = base[i], v2 = base[i + 32];
    base[i]      = tf32r(v1 * c - v2 * s);
    base[i + 32] = tf32r(v2 * c + v1 * s);
}

__global__ void softmax_causal_k(float* __restrict__ S)
{
    int p  = blockIdx.x;
    int bh = blockIdx.y;
    float* row = S + ((long long)bh * PP + p) * PP;
    int tid = threadIdx.x;
    float vals[8];
    float mx = -3.0e38f;
#pragma unroll
    for (int l = 0; l < 8; l++) {
        int c = tid + l * 256;
        float v = row[c];
        if (c > p) v = -1.0e9f;
        vals[l] = v;
        mx = fmaxf(mx, v);
    }
    __shared__ float sm[256];
    sm[tid] = mx; __syncthreads();
    for (int s = 128; s > 0; s >>= 1) {
        if (tid < s) sm[tid] = fmaxf(sm[tid], sm[tid + s]);
        __syncthreads();
    }
    mx = sm[0]; __syncthreads();
    float sum = 0.0f;
#pragma unroll
    for (int l = 0; l < 8; l++) {
        vals[l] = expf(vals[l] - mx);
        sum += vals[l];
    }
    sm[tid] = sum; __syncthreads();
    for (int s = 128; s > 0; s >>= 1) {
        if (tid < s) sm[tid] += sm[tid + s];
        __syncthreads();
    }
    float inv = 1.0f / sm[0];
#pragma unroll
    for (int l = 0; l < 8; l++)
        row[tid + l * 256] = tf32r(vals[l] * inv);
}

__global__ void silu_mul_k(const float* __restrict__ g, const float* __restrict__ u,
                           float* __restrict__ out, long long n)
{
    long long i = (long long)blockIdx.x * blockDim.x + threadIdx.x;
    if (i >= n) return;
    float x = g[i];
    float s = x / (1.0f + expf(-x));
    out[i] = tf32r(s * u[i]);
}

__global__ void expert_act_k(const float* __restrict__ g, const float* __restrict__ u,
                             const float* __restrict__ mask, float* __restrict__ out)
{
    long long i = (long long)blockIdx.x * blockDim.x + threadIdx.x;
    if (i >= (long long)TOK * (NE * FEXP)) return;
    long long t = i >> 12;
    int col = (int)(i & (NE * FEXP - 1));
    int e = col >> 8;
    float x = g[i];
    float s = x / (1.0f + expf(-x));
    out[i] = tf32r(s * u[i] * mask[t * NE + e]);
}

// ---------------- host side ----------------
static void launch_gemm(const float* A, long long sAz, int lda,
                        const float* B, long long sBz, int ldb,
                        float* C, long long sCz, int ldc,
                        const float* bias, const float* R, long long sRz, int ldr,
                        int M, int N, int K, float alpha, int acc, int rnd, int vtrans,
                        int batch)
{
    GemmArgs a;
    a.A = A; a.B = B; a.C = C; a.bias = bias; a.R = R;
    a.sAz = sAz; a.sBz = sBz; a.sCz = sCz; a.sRz = sRz;
    a.lda = lda; a.ldb = ldb; a.ldc = ldc; a.ldr = ldr;
    a.N = N; a.K = K; a.alpha = alpha; a.accumulate = acc; a.round_out = rnd;
    a.vtrans = vtrans;
    dim3 grid((N + 127) / 128, M / 128, batch);
    tf32_gemm_k<<<grid, 128, SMEM_T_BYTES>>>(a);
}

static void launch_cvtw_t(const float* src, float* dst, int K, int Nn, int z)
{
    dim3 grid(K / 32, Nn / 32, z), blk(32, 8);
    cvtw_t_k<<<grid, blk>>>(src, dst, K, Nn);
}

extern "C" void kernel_launch(void* const* d_in, const int* in_sizes, int n_in,
                              void* d_out, int out_size)
{
    const float* x           = (const float*)d_in[0];
    const float* expert_mask = (const float*)d_in[1];
    const float* ln1_w       = (const float*)d_in[2];
    const float* wq          = (const float*)d_in[3];
    const float* bq          = (const float*)d_in[4];
    const float* wk          = (const float*)d_in[5];
    const float* bk          = (const float*)d_in[6];
    const float* wv          = (const float*)d_in[7];
    const float* bv          = (const float*)d_in[8];
    const float* wo          = (const float*)d_in[9];
    const float* ln2_w       = (const float*)d_in[10];
    const float* w_gate      = (const float*)d_in[11];
    const float* w_up        = (const float*)d_in[12];
    const float* w_down      = (const float*)d_in[13];
    const float* we_gate     = (const float*)d_in[14];
    const float* we_up       = (const float*)d_in[15];
    const float* we_down     = (const float*)d_in[16];
    float* out = (float*)d_out;

    cudaFuncSetAttribute(tf32_gemm_k, cudaFuncAttributeMaxDynamicSharedMemorySize, SMEM_T_BYTES);
    cudaFuncSetAttribute(attn_s_k,    cudaFuncAttributeMaxDynamicSharedMemorySize, SMEM_T_BYTES);
    cudaFuncSetAttribute(attn_pv_k,   cudaFuncAttributeMaxDynamicSharedMemorySize, SMEM_T_BYTES);

    float *h, *q, *k, *v, *S, *o, *b1, *b2, *w;
    cudaGetSymbolAddress((void**)&h,  g_h);
    cudaGetSymbolAddress((void**)&q,  g_q);
    cudaGetSymbolAddress((void**)&k,  g_k);
    cudaGetSymbolAddress((void**)&v,  g_v);
    cudaGetSymbolAddress((void**)&S,  g_S);
    cudaGetSymbolAddress((void**)&o,  g_o);
    cudaGetSymbolAddress((void**)&b1, g_b1);
    cudaGetSymbolAddress((void**)&b2, g_b2);
    cudaGetSymbolAddress((void**)&w,  g_w);

    // 0. transpose + tf32-round all weights: stored [N][K]
    launch_cvtw_t(wq,      w + OFF_WQ, DM, NH * HDIM,  1);
    launch_cvtw_t(wk,      w + OFF_WK, DM, NKV * HDIM, 1);
    launch_cvtw_t(wv,      w + OFF_WV, DM, NKV * HDIM, 1);
    launch_cvtw_t(wo,      w + OFF_WO, NH * HDIM, DM,  1);
    launch_cvtw_t(w_gate,  w + OFF_WG, DM, FF, 1);
    launch_cvtw_t(w_up,    w + OFF_WU, DM, FF, 1);
    launch_cvtw_t(w_down,  w + OFF_WD, FF, DM, 1);
    launch_cvtw_t(we_gate, w + OFF_EG, DM, FEXP, NE);
    launch_cvtw_t(we_up,   w + OFF_EU, DM, FEXP, NE);
    launch_cvtw_t(we_down, w + OFF_ED, NE * FEXP, DM, 1);

    // 1. h = rmsnorm(x, ln1_w)
    rmsnorm_k<<<TOK, 256>>>(x, ln1_w, h);

    // 2. q/k/v projections (+bias); v written TRANSPOSED + rounded
    launch_gemm(h, 0, DM, w + OFF_WQ, 0, DM, q, 0, NH * HDIM,  bq, 0, 0, 0,
                TOK, NH * HDIM,  DM, 1.0f, 0, 0, 0, 1);
    launch_gemm(h, 0, DM, w + OFF_WK, 0, DM, k, 0, NKV * HDIM, bk, 0, 0, 0,
                TOK, NKV * HDIM, DM, 1.0f, 0, 0, 0, 1);
    launch_gemm(h, 0, DM, w + OFF_WV, 0, DM, v, 0, 0,          bv, 0, 0, 0,
                TOK, NKV * HDIM, DM, 1.0f, 0, 1, 1, 1);

    // 3. RoPE on q and k
    rope_k<<<(TOK * NH  * 32 + 255) / 256, 256>>>(q, NH);
    rope_k<<<(TOK * NKV * 32 + 255) / 256, 256>>>(k, NKV);

    // 4. S = QK^T / 8  (causal block skip)
    {
        dim3 grid(PP / 128, PP / 128, BHT);
        attn_s_k<<<grid, 128, SMEM_T_BYTES>>>(q, k, S);
    }

    // 5. causal softmax in-place
    {
        dim3 grid(PP, BHT);
        softmax_causal_k<<<grid, 256>>>(S);
    }

    // 6. O = P @ V^T-layout
    {
        dim3 grid(1, PP / 128, BHT);
        attn_pv_k<<<grid, 128, SMEM_T_BYTES>>>(S, v, o);
    }

    // 7. out = x + O @ wo
    launch_gemm(o, 0, NH * HDIM, w + OFF_WO, 0, NH * HDIM, out, 0, DM,
                (const float*)0, x, 0, DM,
                TOK, DM, NH * HDIM, 1.0f, 0, 0, 0, 1);

    // 8. h2 = rmsnorm(out, ln2_w)
    rmsnorm_k<<<TOK, 256>>>(out, ln2_w, h);

    // 9. dense MLP
    launch_gemm(h, 0, DM, w + OFF_WG, 0, DM, b1, 0, FF, (const float*)0,
                (const float*)0, 0, 0, TOK, FF, DM, 1.0f, 0, 0, 0, 1);
    launch_gemm(h, 0, DM, w + OFF_WU, 0, DM, b2, 0, FF, (const float*)0,
                (const float*)0, 0, 0, TOK, FF, DM, 1.0f, 0, 0, 0, 1);
    {
        long long n = (long long)TOK * FF;
        silu_mul_k<<<(unsigned)((n + 255) / 256), 256>>>(b1, b2, b1, n);
    }
    launch_gemm(b1, 0, FF, w + OFF_WD, 0, FF, out, 0, DM, (const float*)0,
                (const float*)0, 0, 0, TOK, DM, FF, 1.0f, 1, 0, 0, 1);

    // 10. experts (batched over e)
    launch_gemm(h, 0, DM, w + OFF_EG, (long long)DM * FEXP, DM,
                b1, FEXP, NE * FEXP, (const float*)0, (const float*)0, 0, 0,
                TOK, FEXP, DM, 1.0f, 0, 0, 0, NE);
    launch_gemm(h, 0, DM, w + OFF_EU, (long long)DM * FEXP, DM,
                b2, FEXP, NE * FEXP, (const float*)0, (const float*)0, 0, 0,
                TOK, FEXP, DM, 1.0f, 0, 0, 0, NE);

    // 11. routed combine + down
    {
        long long n = (long long)TOK * NE * FEXP;
        expert_act_k<<<(unsigned)((n + 255) / 256), 256>>>(b1, b2, expert_mask, b1);
    }
    launch_gemm(b1, 0, NE * FEXP, w + OFF_ED, 0, NE * FEXP, out, 0, DM, (const float*)0,
                (const float*)0, 0, 0, TOK, DM, NE * FEXP, 1.0f, 1, 0, 0, 1);
}